// round 12
// baseline (speedup 1.0000x reference)
#include <cuda_runtime.h>
#include <cuda_fp16.h>

#define NN 50000
#define NE 1600000
#define DD 32
static constexpr float Hstep = 0.1f;

// ---------------- static device scratch ----------------
__device__ int      g_is64;
__device__ int      g_deg[2][NN];
__device__ int      g_cur[2][NN];
__device__ int      g_rowptr[2][NN + 1];
__device__ __align__(16) unsigned g_colval[2][NE];   // low16 = col, high16 = fp16 val
__device__ float    g_dis[2][NN];
__device__ __align__(16) unsigned g_tq[2][2][NN * 8]; // [ping][branch] int8 rows (excess-128)
__device__ float    g_sc[2][2][NN];                   // [ping][branch] per-row scales
__device__ __align__(128) float g_x[2 * NN * DD];
__device__ __align__(128) float g_ksum[2 * NN * DD];

// ---------------- edge readers (dtype-agnostic) ----------------
__device__ __forceinline__ int edge_src(const void* ei, int e, int is64) {
    if (is64) return (int)((const long long*)ei)[e];
    return ((const int*)ei)[e];
}
__device__ __forceinline__ int edge_dst(const void* ei, int e, int is64) {
    if (is64) return (int)((const long long*)ei)[NE + e];
    return ((const int*)ei)[NE + e];
}

// int8 dequant-accumulate: bytes of m are excess-128; adds vs*(b-128) per dim
__device__ __forceinline__ void deq_acc(float4& acc, unsigned m, float vs) {
    const float C = 8388736.0f;  // 2^23 + 128
    acc.x += vs * (__uint_as_float(__byte_perm(m, 0x4B000000u, 0x7540)) - C);
    acc.y += vs * (__uint_as_float(__byte_perm(m, 0x4B000000u, 0x7541)) - C);
    acc.z += vs * (__uint_as_float(__byte_perm(m, 0x4B000000u, 0x7542)) - C);
    acc.w += vs * (__uint_as_float(__byte_perm(m, 0x4B000000u, 0x7543)) - C);
}

// ---------------- setup: probe dtype + zero both degree arrays ----------------
__global__ void k_probe_zero(const int* __restrict__ w) {
    if (blockIdx.x == 0) {
        __shared__ int anynz;
        if (threadIdx.x == 0) anynz = 0;
        __syncthreads();
        if (w[2 * threadIdx.x + 1] != 0) atomicOr(&anynz, 1);
        __syncthreads();
        if (threadIdx.x == 0) g_is64 = (anynz == 0) ? 1 : 0;
    }
    int i = blockIdx.x * blockDim.x + threadIdx.x;
    int stride = gridDim.x * blockDim.x;
    for (; i < 2 * NN; i += stride) ((int*)g_deg)[i] = 0;
}

// both branches: blocks [0,H) -> pos, [H,2H) -> neg
__global__ void k_hist(const void* __restrict__ epos, const void* __restrict__ eneg) {
    const int H = gridDim.x >> 1;
    const int br = blockIdx.x >= H;
    const void* ei = br ? eneg : epos;
    const int bb = blockIdx.x - br * H;
    const int is64 = g_is64;
    int stride = H * blockDim.x;
    for (int e = bb * blockDim.x + threadIdx.x; e < NE; e += stride)
        atomicAdd(&g_deg[br][edge_dst(ei, e, is64)], 1);
}

// block b = branch b: dis + exclusive scan -> rowptr, cur
__global__ void k_scan_dis() {
    const int b = blockIdx.x;
    __shared__ int sm[1024];
    const int tid = threadIdx.x;
    const int CH = (NN + 1023) / 1024;  // 49
    int base = tid * CH;
    int s = 0;
    for (int i = 0; i < CH; i++) {
        int idx = base + i;
        if (idx < NN) {
            int d = g_deg[b][idx];
            g_dis[b][idx] = rsqrtf((float)d + 1.0f);
            s += d;
        }
    }
    sm[tid] = s;
    __syncthreads();
    for (int off = 1; off < 1024; off <<= 1) {
        int v = (tid >= off) ? sm[tid - off] : 0;
        __syncthreads();
        sm[tid] += v;
        __syncthreads();
    }
    int run = (tid == 0) ? 0 : sm[tid - 1];
    for (int i = 0; i < CH; i++) {
        int idx = base + i;
        if (idx < NN) {
            g_rowptr[b][idx] = run;
            g_cur[b][idx] = run;
            run += g_deg[b][idx];
        }
    }
    if (tid == 1023) g_rowptr[b][NN] = sm[1023];
}

// blocks [0,EB): scatter pos; [EB,2EB): scatter neg; rest: init x / quantized tin
__global__ void __launch_bounds__(256) k_scatter_init(
    const void* __restrict__ epos, const void* __restrict__ eneg,
    const float* __restrict__ x0, int EB) {
    if (blockIdx.x < 2 * EB) {
        const int br = blockIdx.x >= EB;
        const void* ei = br ? eneg : epos;
        const int bb = blockIdx.x - br * EB;
        const int is64 = g_is64;
        int stride = EB * blockDim.x;
        for (int e = bb * blockDim.x + threadIdx.x; e < NE; e += stride) {
            int s = edge_src(ei, e, is64);
            int d = edge_dst(ei, e, is64);
            int p = atomicAdd(&g_cur[br][d], 1);
            __half hv = __float2half(g_dis[br][s] * g_dis[br][d]);
            g_colval[br][p] = (unsigned)s | ((unsigned)__half_as_ushort(hv) << 16);
        }
    } else {
        const int lane = threadIdx.x & 31;
        const int li = lane & 7;
        int warpId = ((blockIdx.x - 2 * EB) * blockDim.x + threadIdx.x) >> 5;
        int nw = ((gridDim.x - 2 * EB) * blockDim.x) >> 5;
        for (int r = warpId; r < NN; r += nw) {
            const int idx = r * 32 + lane;
            float xv = x0[idx];
            g_x[idx] = xv;
            g_x[NN * DD + idx] = xv;
            float ay = fabsf(xv);
#pragma unroll
            for (int off = 16; off; off >>= 1)
                ay = fmaxf(ay, __shfl_xor_sync(0xffffffffu, ay, off));
            float inv = ay > 0.f ? 127.0f / ay : 0.f;
            int q = __float2int_rn(xv * inv);
            unsigned qb = (unsigned)(q + 128);
            unsigned w = __shfl_sync(0xffffffffu, qb, 4 * li)
                       | (__shfl_sync(0xffffffffu, qb, 4 * li + 1) << 8)
                       | (__shfl_sync(0xffffffffu, qb, 4 * li + 2) << 16)
                       | (__shfl_sync(0xffffffffu, qb, 4 * li + 3) << 24);
            if (lane < 8) {
                g_tq[0][0][(size_t)r * 8 + lane] = w;
                g_tq[0][1][(size_t)r * 8 + lane] = w;
            }
            if (lane == 0) {
                float sc = ay * (1.0f / 127.0f);
                g_sc[0][0][r] = sc;
                g_sc[0][1][r] = sc;
            }
        }
    }
}

// ---------------- fused RK4 stage, both branches, int8 gather, deferred @W ----
template <int STAGE>
__global__ void __launch_bounds__(256) k_stage(
    int pin,
    const float* __restrict__ Wp, const float* __restrict__ bp, const float* __restrict__ wtp,
    const float* __restrict__ Wn, const float* __restrict__ bn, const float* __restrict__ wtn,
    float t, float* __restrict__ xout) {
    const int H = gridDim.x >> 1;
    const int br = blockIdx.x >= H;
    const float* __restrict__ W = br ? Wn : Wp;
    const float* __restrict__ bvec = br ? bn : bp;
    const float* __restrict__ wt = br ? wtn : wtp;
    const unsigned* __restrict__ colval = g_colval[br];
    const int* __restrict__ rowptr = g_rowptr[br];
    const float* __restrict__ dis = g_dis[br];
    const size_t boff = (size_t)br * NN * DD;
    const unsigned* __restrict__ tq_in = g_tq[pin][br];
    unsigned* __restrict__ tq_out = g_tq[pin ^ 1][br];
    const float* __restrict__ sc_in = g_sc[pin][br];
    float* __restrict__ sc_out = g_sc[pin ^ 1][br];
    const float* __restrict__ xbase = g_x + boff;
    float* __restrict__ xw = g_x + boff;
    float* __restrict__ ksb = g_ksum + boff;

    __shared__ float Wt[DD * 36];        // transposed W, row stride 36 floats
    __shared__ float zbuf[8][DD];
    {
        int tid = threadIdx.x;
        for (int idx = tid; idx < DD * DD; idx += 256) {
            int d = idx >> 5, l = idx & 31;
            Wt[l * 36 + d] = W[idx];
        }
    }
    __syncthreads();

    const int lane = threadIdx.x & 31;
    const int wid = threadIdx.x >> 5;
    const int li = lane & 7;
    const int g = lane >> 3;

    const float bb = __ldg(&bvec[lane]);
    const float gate = 1.0f / (1.0f + __expf(-t * __ldg(&wt[lane])));

    int warpLocal = (blockIdx.x - br * H) * 8 + wid;
    const int nwarps = H * 8;

    for (int r = warpLocal; r < NN; r += nwarps) {
        const int st = rowptr[r];
        const int en = rowptr[r + 1];
        float4 acc = make_float4(0.f, 0.f, 0.f, 0.f);

        // peel to 4-alignment (group g takes edge st+g)
        int pre = en - st;
        if (pre > ((4 - (st & 3)) & 3)) pre = (4 - (st & 3)) & 3;
        if (g < pre) {
            unsigned cv = __ldg(&colval[st + g]);
            int src = (int)(cv & 0xFFFFu);
            float v = __half2float(__ushort_as_half((unsigned short)(cv >> 16)));
            float vs = v * __ldg(&sc_in[src]);
            unsigned m = __ldg(&tq_in[(size_t)src * 8 + li]);
            deq_acc(acc, m, vs);
        }
        int e = st + pre;
        // batch-16: group g loads colval[e+4g..e+4g+3] as one uint4, 4 gathers
        for (; e + 16 <= en; e += 16) {
            const uint4 cv = __ldg((const uint4*)&colval[e + 4 * g]);
            const int s0 = (int)(cv.x & 0xFFFFu);
            const int s1 = (int)(cv.y & 0xFFFFu);
            const int s2 = (int)(cv.z & 0xFFFFu);
            const int s3 = (int)(cv.w & 0xFFFFu);
            const float sa = __ldg(&sc_in[s0]);
            const float sb = __ldg(&sc_in[s1]);
            const float sc = __ldg(&sc_in[s2]);
            const float sd = __ldg(&sc_in[s3]);
            const unsigned m0 = __ldg(&tq_in[(size_t)s0 * 8 + li]);
            const unsigned m1 = __ldg(&tq_in[(size_t)s1 * 8 + li]);
            const unsigned m2 = __ldg(&tq_in[(size_t)s2 * 8 + li]);
            const unsigned m3 = __ldg(&tq_in[(size_t)s3 * 8 + li]);
            deq_acc(acc, m0, __half2float(__ushort_as_half((unsigned short)(cv.x >> 16))) * sa);
            deq_acc(acc, m1, __half2float(__ushort_as_half((unsigned short)(cv.y >> 16))) * sb);
            deq_acc(acc, m2, __half2float(__ushort_as_half((unsigned short)(cv.z >> 16))) * sc);
            deq_acc(acc, m3, __half2float(__ushort_as_half((unsigned short)(cv.w >> 16))) * sd);
        }
        // remainder: group g takes every 4th
        for (int ee = e + g; ee < en; ee += 4) {
            unsigned cv = __ldg(&colval[ee]);
            int src = (int)(cv & 0xFFFFu);
            float v = __half2float(__ushort_as_half((unsigned short)(cv >> 16)));
            float vs = v * __ldg(&sc_in[src]);
            unsigned m = __ldg(&tq_in[(size_t)src * 8 + li]);
            deq_acc(acc, m, vs);
        }
        // combine 4 group partials (lanes with equal li)
#pragma unroll
        for (int off = 8; off < 32; off <<= 1) {
            acc.x += __shfl_xor_sync(0xffffffffu, acc.x, off);
            acc.y += __shfl_xor_sync(0xffffffffu, acc.y, off);
            acc.z += __shfl_xor_sync(0xffffffffu, acc.z, off);
            acc.w += __shfl_xor_sync(0xffffffffu, acc.w, off);
        }
        // self term (all lanes compute identically)
        {
            const float dn = dis[r];
            const float vs = dn * dn * sc_in[r];
            const unsigned m = __ldg(&tq_in[(size_t)r * 8 + li]);
            deq_acc(acc, m, vs);
        }
        // z -> smem (group 0), then per-lane u = z @ W[:,lane]
        if (g == 0) ((float4*)zbuf[wid])[li] = acc;
        __syncwarp();
        float u = 0.f;
        {
            const float4* zp = (const float4*)zbuf[wid];
            const float4* wp = (const float4*)&Wt[lane * 36];
#pragma unroll
            for (int q = 0; q < 8; q++) {
                const float4 zq = zp[q];
                const float4 wq = wp[q];
                u += zq.x * wq.x + zq.y * wq.y + zq.z * wq.z + zq.w * wq.w;
            }
        }
        __syncwarp();

        const float k = fmaxf(u + bb, 0.f) * gate;
        const int idx = r * 32 + lane;
        const float xv = xbase[idx];
        float y;
        if (STAGE == 1) {
            ksb[idx] = k;
            y = xv + 0.5f * Hstep * k;
        } else if (STAGE == 2) {
            ksb[idx] += 2.f * k;
            y = xv + 0.5f * Hstep * k;
        } else if (STAGE == 3) {
            ksb[idx] += 2.f * k;
            y = xv + Hstep * k;
        } else {
            y = xv + (Hstep / 6.f) * (ksb[idx] + k);
            if (xout) xout[boff + idx] = y;
            else      xw[idx] = y;
        }

        // quantize y row -> tq_out + sc_out
        float ay = fabsf(y);
#pragma unroll
        for (int off = 16; off; off >>= 1)
            ay = fmaxf(ay, __shfl_xor_sync(0xffffffffu, ay, off));
        float inv = ay > 0.f ? 127.0f / ay : 0.f;
        int q = __float2int_rn(y * inv);
        unsigned qb = (unsigned)(q + 128);
        unsigned w = __shfl_sync(0xffffffffu, qb, 4 * li)
                   | (__shfl_sync(0xffffffffu, qb, 4 * li + 1) << 8)
                   | (__shfl_sync(0xffffffffu, qb, 4 * li + 2) << 16)
                   | (__shfl_sync(0xffffffffu, qb, 4 * li + 3) << 24);
        if (lane < 8) tq_out[(size_t)r * 8 + lane] = w;
        if (lane == 0) sc_out[r] = ay * (1.0f / 127.0f);
    }
}

// ---------------- host ----------------
extern "C" void kernel_launch(void* const* d_in, const int* in_sizes, int n_in,
                              void* d_out, int out_size) {
    const float* x0 = (const float*)d_in[0];
    const void* epos = d_in[1];
    const void* eneg = d_in[2];
    const float* Wp = (const float*)d_in[3];
    const float* bp = (const float*)d_in[4];
    const float* wtp = (const float*)d_in[5];
    const float* Wn = (const float*)d_in[6];
    const float* bn = (const float*)d_in[7];
    const float* wtn = (const float*)d_in[8];
    float* out = (float*)d_out;

    const int STAGE_BLOCKS = 592;  // 296 per branch
    const int EB = 1184;

    k_probe_zero<<<196, 256>>>((const int*)epos);
    k_hist<<<2 * EB, 256>>>(epos, eneg);
    k_scan_dis<<<2, 1024>>>();
    k_scatter_init<<<2 * EB + 296, 256>>>(epos, eneg, x0, EB);

    int pin = 0;
    for (int step = 0; step < 10; step++) {
        float t = step * Hstep;
        k_stage<1><<<STAGE_BLOCKS, 256>>>(pin, Wp, bp, wtp, Wn, bn, wtn, t, nullptr);
        pin ^= 1;
        k_stage<2><<<STAGE_BLOCKS, 256>>>(pin, Wp, bp, wtp, Wn, bn, wtn, t + 0.5f * Hstep, nullptr);
        pin ^= 1;
        k_stage<3><<<STAGE_BLOCKS, 256>>>(pin, Wp, bp, wtp, Wn, bn, wtn, t + 0.5f * Hstep, nullptr);
        pin ^= 1;
        float* xo = (step == 9) ? out : nullptr;
        k_stage<4><<<STAGE_BLOCKS, 256>>>(pin, Wp, bp, wtp, Wn, bn, wtn, t + Hstep, xo);
        pin ^= 1;
    }
}

// round 13
// speedup vs baseline: 1.3328x; 1.3328x over previous
#include <cuda_runtime.h>
#include <cuda_fp16.h>

#define NN 50000
#define NE 1600000
#define DD 32
static constexpr float Hstep = 0.1f;

// ---------------- static device scratch ----------------
__device__ int      g_is64;
__device__ int      g_deg[2][NN];
__device__ int      g_cur[2][NN];
__device__ int      g_rowptr[2][NN + 1];
__device__ __align__(16) unsigned g_colval[2][NE];   // low16 = col, high16 = fp16 val
__device__ float    g_dis[2][NN];
__device__ __align__(16) __half g_tmph[2][2 * NN * DD];  // ping-pong y buffers, both branches
__device__ __align__(128) float g_x[2 * NN * DD];
__device__ __align__(128) float g_ksum[2 * NN * DD];

// ---------------- edge readers (dtype-agnostic) ----------------
__device__ __forceinline__ int edge_src(const void* ei, int e, int is64) {
    if (is64) return (int)((const long long*)ei)[e];
    return ((const int*)ei)[e];
}
__device__ __forceinline__ int edge_dst(const void* ei, int e, int is64) {
    if (is64) return (int)((const long long*)ei)[NE + e];
    return ((const int*)ei)[NE + e];
}

// ---------------- setup: probe dtype + zero both degree arrays ----------------
__global__ void k_probe_zero(const int* __restrict__ w) {
    if (blockIdx.x == 0) {
        __shared__ int anynz;
        if (threadIdx.x == 0) anynz = 0;
        __syncthreads();
        if (w[2 * threadIdx.x + 1] != 0) atomicOr(&anynz, 1);
        __syncthreads();
        if (threadIdx.x == 0) g_is64 = (anynz == 0) ? 1 : 0;
    }
    int i = blockIdx.x * blockDim.x + threadIdx.x;
    int stride = gridDim.x * blockDim.x;
    for (; i < 2 * NN; i += stride) ((int*)g_deg)[i] = 0;
}

// both branches: blocks [0,H) -> pos, [H,2H) -> neg
__global__ void k_hist(const void* __restrict__ epos, const void* __restrict__ eneg) {
    const int H = gridDim.x >> 1;
    const int br = blockIdx.x >= H;
    const void* ei = br ? eneg : epos;
    const int bb = blockIdx.x - br * H;
    const int is64 = g_is64;
    int stride = H * blockDim.x;
    for (int e = bb * blockDim.x + threadIdx.x; e < NE; e += stride)
        atomicAdd(&g_deg[br][edge_dst(ei, e, is64)], 1);
}

// block b = branch b: dis + exclusive scan -> rowptr, cur
__global__ void k_scan_dis() {
    const int b = blockIdx.x;
    __shared__ int sm[1024];
    const int tid = threadIdx.x;
    const int CH = (NN + 1023) / 1024;  // 49
    int base = tid * CH;
    int s = 0;
    for (int i = 0; i < CH; i++) {
        int idx = base + i;
        if (idx < NN) {
            int d = g_deg[b][idx];
            g_dis[b][idx] = rsqrtf((float)d + 1.0f);
            s += d;
        }
    }
    sm[tid] = s;
    __syncthreads();
    for (int off = 1; off < 1024; off <<= 1) {
        int v = (tid >= off) ? sm[tid - off] : 0;
        __syncthreads();
        sm[tid] += v;
        __syncthreads();
    }
    int run = (tid == 0) ? 0 : sm[tid - 1];
    for (int i = 0; i < CH; i++) {
        int idx = base + i;
        if (idx < NN) {
            g_rowptr[b][idx] = run;
            g_cur[b][idx] = run;
            run += g_deg[b][idx];
        }
    }
    if (tid == 1023) g_rowptr[b][NN] = sm[1023];
}

// blocks [0,EB): scatter pos; [EB,2EB): scatter neg; rest: init x / tin
__global__ void __launch_bounds__(256) k_scatter_init(
    const void* __restrict__ epos, const void* __restrict__ eneg,
    const float* __restrict__ x0, int EB) {
    if (blockIdx.x < 2 * EB) {
        const int br = blockIdx.x >= EB;
        const void* ei = br ? eneg : epos;
        const int bb = blockIdx.x - br * EB;
        const int is64 = g_is64;
        int stride = EB * blockDim.x;
        for (int e = bb * blockDim.x + threadIdx.x; e < NE; e += stride) {
            int s = edge_src(ei, e, is64);
            int d = edge_dst(ei, e, is64);
            int p = atomicAdd(&g_cur[br][d], 1);
            __half hv = __float2half(g_dis[br][s] * g_dis[br][d]);
            g_colval[br][p] = (unsigned)s | ((unsigned)__half_as_ushort(hv) << 16);
        }
    } else {
        int i = (blockIdx.x - 2 * EB) * blockDim.x + threadIdx.x;
        int stride = (gridDim.x - 2 * EB) * blockDim.x;
        for (; i < 2 * NN * DD; i += stride) {
            float v = x0[i >= NN * DD ? i - NN * DD : i];
            g_x[i] = v;
            g_tmph[0][i] = __float2half(v);
        }
    }
}

// ---------------- fused RK4 stage, both branches, deferred @W ----------------
// Gather raw y (fp16): z = sum v*y_src + selfnorm*y_r; u = z @ W;
// k = relu(u + b)*gate; RK4 update scalar-per-lane; store y' (fp16) to tout.
template <int STAGE>
__global__ void __launch_bounds__(256, 4) k_stage(
    int pin,
    const float* __restrict__ Wp, const float* __restrict__ bp, const float* __restrict__ wtp,
    const float* __restrict__ Wn, const float* __restrict__ bn, const float* __restrict__ wtn,
    float t, float* __restrict__ xout) {
    const int H = gridDim.x >> 1;
    const int br = blockIdx.x >= H;
    const float* __restrict__ W = br ? Wn : Wp;
    const float* __restrict__ bvec = br ? bn : bp;
    const float* __restrict__ wt = br ? wtn : wtp;
    const unsigned* __restrict__ colval = g_colval[br];
    const int* __restrict__ rowptr = g_rowptr[br];
    const float* __restrict__ dis = g_dis[br];
    const size_t boff = (size_t)br * NN * DD;
    const uint2* __restrict__ tin_v = (const uint2*)(g_tmph[pin]) + (size_t)br * NN * 8;
    __half* __restrict__ tout = g_tmph[pin ^ 1] + boff;
    const float* __restrict__ xbase = g_x + boff;
    float* __restrict__ xw = g_x + boff;
    float* __restrict__ ksb = g_ksum + boff;

    __shared__ float Wt[DD * 36];        // transposed W, row stride 36 floats
    __shared__ float zbuf[8][DD];
    {
        int tid = threadIdx.x;
        for (int idx = tid; idx < DD * DD; idx += 256) {
            int d = idx >> 5, l = idx & 31;
            Wt[l * 36 + d] = W[idx];
        }
    }
    __syncthreads();

    const int lane = threadIdx.x & 31;
    const int wid = threadIdx.x >> 5;
    const int li = lane & 7;
    const int g = lane >> 3;

    const float bb = __ldg(&bvec[lane]);
    const float gate = 1.0f / (1.0f + __expf(-t * __ldg(&wt[lane])));

    int warpLocal = (blockIdx.x - br * H) * 8 + wid;
    const int nwarps = H * 8;

    for (int r = warpLocal; r < NN; r += nwarps) {
        const int st = rowptr[r];
        const int en = rowptr[r + 1];
        float4 acc = make_float4(0.f, 0.f, 0.f, 0.f);

        // peel to 4-alignment (group g takes edge st+g)
        int pre = en - st;
        if (pre > ((4 - (st & 3)) & 3)) pre = (4 - (st & 3)) & 3;
        if (g < pre) {
            unsigned cv = __ldg(&colval[st + g]);
            float v = __half2float(__ushort_as_half((unsigned short)(cv >> 16)));
            union { uint2 u; __half2 h[2]; } rw;
            rw.u = __ldg(&tin_v[(size_t)(cv & 0xFFFFu) * 8 + li]);
            float2 a01 = __half22float2(rw.h[0]);
            float2 a23 = __half22float2(rw.h[1]);
            acc.x += v * a01.x; acc.y += v * a01.y;
            acc.z += v * a23.x; acc.w += v * a23.y;
        }
        int e = st + pre;
        const int nbatch = (en - e) >> 4;   // 16-edge batches
        // software-pipelined: colval for batch i+1 prefetched during batch i
        uint4 cv;
        if (nbatch > 0) cv = __ldg((const uint4*)&colval[e + 4 * g]);
        for (int it = 0; it < nbatch; it++) {
            union { uint2 u; __half2 h[2]; } r0, r1, r2, r3;
            r0.u = __ldg(&tin_v[(size_t)(cv.x & 0xFFFFu) * 8 + li]);
            r1.u = __ldg(&tin_v[(size_t)(cv.y & 0xFFFFu) * 8 + li]);
            r2.u = __ldg(&tin_v[(size_t)(cv.z & 0xFFFFu) * 8 + li]);
            r3.u = __ldg(&tin_v[(size_t)(cv.w & 0xFFFFu) * 8 + li]);
            uint4 cvn = cv;
            if (it + 1 < nbatch)
                cvn = __ldg((const uint4*)&colval[e + 16 * (it + 1) + 4 * g]);
            float v; float2 a;
            v = __half2float(__ushort_as_half((unsigned short)(cv.x >> 16)));
            a = __half22float2(r0.h[0]); acc.x += v * a.x; acc.y += v * a.y;
            a = __half22float2(r0.h[1]); acc.z += v * a.x; acc.w += v * a.y;
            v = __half2float(__ushort_as_half((unsigned short)(cv.y >> 16)));
            a = __half22float2(r1.h[0]); acc.x += v * a.x; acc.y += v * a.y;
            a = __half22float2(r1.h[1]); acc.z += v * a.x; acc.w += v * a.y;
            v = __half2float(__ushort_as_half((unsigned short)(cv.z >> 16)));
            a = __half22float2(r2.h[0]); acc.x += v * a.x; acc.y += v * a.y;
            a = __half22float2(r2.h[1]); acc.z += v * a.x; acc.w += v * a.y;
            v = __half2float(__ushort_as_half((unsigned short)(cv.w >> 16)));
            a = __half22float2(r3.h[0]); acc.x += v * a.x; acc.y += v * a.y;
            a = __half22float2(r3.h[1]); acc.z += v * a.x; acc.w += v * a.y;
            cv = cvn;
        }
        e += nbatch << 4;
        // remainder: group g takes every 4th
        for (int ee = e + g; ee < en; ee += 4) {
            unsigned cvs = __ldg(&colval[ee]);
            float v = __half2float(__ushort_as_half((unsigned short)(cvs >> 16)));
            union { uint2 u; __half2 h[2]; } rw;
            rw.u = __ldg(&tin_v[(size_t)(cvs & 0xFFFFu) * 8 + li]);
            float2 a01 = __half22float2(rw.h[0]);
            float2 a23 = __half22float2(rw.h[1]);
            acc.x += v * a01.x; acc.y += v * a01.y;
            acc.z += v * a23.x; acc.w += v * a23.y;
        }
        // combine 4 group partials (lanes with equal li)
#pragma unroll
        for (int off = 8; off < 32; off <<= 1) {
            acc.x += __shfl_xor_sync(0xffffffffu, acc.x, off);
            acc.y += __shfl_xor_sync(0xffffffffu, acc.y, off);
            acc.z += __shfl_xor_sync(0xffffffffu, acc.z, off);
            acc.w += __shfl_xor_sync(0xffffffffu, acc.w, off);
        }
        // self term (all lanes compute identically)
        {
            const float dn = dis[r];
            const float sn = dn * dn;
            union { uint2 u; __half2 h[2]; } swv;
            swv.u = __ldg(&tin_v[(size_t)r * 8 + li]);
            float2 s01 = __half22float2(swv.h[0]);
            float2 s23 = __half22float2(swv.h[1]);
            acc.x += sn * s01.x; acc.y += sn * s01.y;
            acc.z += sn * s23.x; acc.w += sn * s23.y;
        }
        // z -> smem (group 0), then per-lane u = z @ W[:,lane]
        if (g == 0) ((float4*)zbuf[wid])[li] = acc;
        __syncwarp();
        float u = 0.f;
        {
            const float4* zp = (const float4*)zbuf[wid];
            const float4* wp = (const float4*)&Wt[lane * 36];
#pragma unroll
            for (int q = 0; q < 8; q++) {
                const float4 zq = zp[q];
                const float4 wq = wp[q];
                u += zq.x * wq.x + zq.y * wq.y + zq.z * wq.z + zq.w * wq.w;
            }
        }
        __syncwarp();

        const float k = fmaxf(u + bb, 0.f) * gate;
        const int idx = r * 32 + lane;
        const float xv = xbase[idx];
        float y;
        if (STAGE == 1) {
            ksb[idx] = k;
            y = xv + 0.5f * Hstep * k;
        } else if (STAGE == 2) {
            ksb[idx] += 2.f * k;
            y = xv + 0.5f * Hstep * k;
        } else if (STAGE == 3) {
            ksb[idx] += 2.f * k;
            y = xv + Hstep * k;
        } else {
            y = xv + (Hstep / 6.f) * (ksb[idx] + k);
            if (xout) xout[boff + idx] = y;
            else      xw[idx] = y;
        }
        tout[idx] = __float2half(y);
    }
}

// ---------------- host ----------------
extern "C" void kernel_launch(void* const* d_in, const int* in_sizes, int n_in,
                              void* d_out, int out_size) {
    const float* x0 = (const float*)d_in[0];
    const void* epos = d_in[1];
    const void* eneg = d_in[2];
    const float* Wp = (const float*)d_in[3];
    const float* bp = (const float*)d_in[4];
    const float* wtp = (const float*)d_in[5];
    const float* Wn = (const float*)d_in[6];
    const float* bn = (const float*)d_in[7];
    const float* wtn = (const float*)d_in[8];
    float* out = (float*)d_out;

    const int STAGE_BLOCKS = 592;  // 4 blocks/SM x 148 SMs; 296 per branch
    const int EB = 1184;

    k_probe_zero<<<196, 256>>>((const int*)epos);
    k_hist<<<2 * EB, 256>>>(epos, eneg);
    k_scan_dis<<<2, 1024>>>();
    k_scatter_init<<<2 * EB + 296, 256>>>(epos, eneg, x0, EB);

    int pin = 0;
    for (int step = 0; step < 10; step++) {
        float t = step * Hstep;
        k_stage<1><<<STAGE_BLOCKS, 256>>>(pin, Wp, bp, wtp, Wn, bn, wtn, t, nullptr);
        pin ^= 1;
        k_stage<2><<<STAGE_BLOCKS, 256>>>(pin, Wp, bp, wtp, Wn, bn, wtn, t + 0.5f * Hstep, nullptr);
        pin ^= 1;
        k_stage<3><<<STAGE_BLOCKS, 256>>>(pin, Wp, bp, wtp, Wn, bn, wtn, t + 0.5f * Hstep, nullptr);
        pin ^= 1;
        float* xo = (step == 9) ? out : nullptr;
        k_stage<4><<<STAGE_BLOCKS, 256>>>(pin, Wp, bp, wtp, Wn, bn, wtn, t + Hstep, xo);
        pin ^= 1;
    }
}